// round 1
// baseline (speedup 1.0000x reference)
#include <cuda_runtime.h>
#include <math.h>

#define BB 64
#define PP 512
#define NN 512
#define EE 128
#define FFD 512
#define LLAYERS 6
#define M_TOT (BB*NN)
#define EPS 1e-5f
#define INV_SQRT_E 0.08838834764831845f  /* 1/sqrt(128) */

// ---------------- scratch (static device globals; no alloc allowed) ----------------
__device__ float g_x  [BB*NN*EE];
__device__ float g_y  [BB*NN*EE];
__device__ float g_h  [BB*NN*EE];
__device__ float g_sq [BB*NN*EE];
__device__ float g_ek [BB*NN*EE];
__device__ float g_ekv[BB*NN*EE];
__device__ float g_hid[BB*NN*FFD];
__device__ float g_aft[BB*PP*EE];
__device__ float g_gq [BB*EE];
__device__ float g_gm [BB*EE];

// ---------------- embedding ----------------
__global__ void embed_kernel(const float* __restrict__ data,
                             const float* __restrict__ W,
                             const float* __restrict__ bias,
                             float* __restrict__ X) {
    int idx = blockIdx.x;            // b*NN + n
    int e   = threadIdx.x;           // 0..127
    float d0 = data[idx*2+0], d1 = data[idx*2+1];
    X[(size_t)idx*EE + e] = d0*W[e] + d1*W[EE+e] + bias[e];
}

// ---------------- qkv GEMM (triple accumulator) ----------------
// X[M,E] @ {Wq,Wk,Wv}[E,E] -> sq=sigmoid(q), ek=exp(k), ekv=ek*v
__global__ void qkv_kernel(const float* __restrict__ X,
                           const float* __restrict__ Wq,
                           const float* __restrict__ Wk,
                           const float* __restrict__ Wv,
                           float* __restrict__ SQ,
                           float* __restrict__ EK,
                           float* __restrict__ EKV) {
    const int m0 = blockIdx.x*64, n0 = blockIdx.y*64;
    __shared__ float As[16][64];
    __shared__ float Bq[16][64], Bk[16][64], Bv[16][64];
    float aq[4][4] = {}, ak[4][4] = {}, av[4][4] = {};
    int tid = threadIdx.x, tx = tid & 15, ty = tid >> 4;

    for (int k0 = 0; k0 < EE; k0 += 16) {
        #pragma unroll
        for (int i = 0; i < 4; i++) {
            int e = tid + i*256; int m = e >> 4, k = e & 15;
            As[k][m] = X[(size_t)(m0+m)*EE + k0 + k];
        }
        #pragma unroll
        for (int i = 0; i < 4; i++) {
            int e = tid + i*256; int k = e >> 6, n = e & 63;
            Bq[k][n] = Wq[(k0+k)*EE + n0 + n];
            Bk[k][n] = Wk[(k0+k)*EE + n0 + n];
            Bv[k][n] = Wv[(k0+k)*EE + n0 + n];
        }
        __syncthreads();
        #pragma unroll
        for (int kk = 0; kk < 16; kk++) {
            float4 a4  = *(const float4*)&As[kk][ty*4];
            float4 q4  = *(const float4*)&Bq[kk][tx*4];
            float4 k4  = *(const float4*)&Bk[kk][tx*4];
            float4 v4  = *(const float4*)&Bv[kk][tx*4];
            float a[4]  = {a4.x, a4.y, a4.z, a4.w};
            float qb[4] = {q4.x, q4.y, q4.z, q4.w};
            float kb[4] = {k4.x, k4.y, k4.z, k4.w};
            float vb[4] = {v4.x, v4.y, v4.z, v4.w};
            #pragma unroll
            for (int i = 0; i < 4; i++)
                #pragma unroll
                for (int j = 0; j < 4; j++) {
                    aq[i][j] += a[i]*qb[j];
                    ak[i][j] += a[i]*kb[j];
                    av[i][j] += a[i]*vb[j];
                }
        }
        __syncthreads();
    }
    #pragma unroll
    for (int i = 0; i < 4; i++)
        #pragma unroll
        for (int j = 0; j < 4; j++) {
            int row = m0 + ty*4 + i, col = n0 + tx*4 + j;
            size_t o = (size_t)row*EE + col;
            SQ[o] = 1.f/(1.f + __expf(-aq[i][j]));
            float ekk = __expf(ak[i][j]);
            EK[o]  = ekk;
            EKV[o] = ekk*av[i][j];
        }
}

// ---------------- dec k/v GEMM (dual accumulator) ----------------
__global__ void deckv_kernel(const float* __restrict__ X,
                             const float* __restrict__ Wk,
                             const float* __restrict__ Wv,
                             float* __restrict__ EK,
                             float* __restrict__ EKV) {
    const int m0 = blockIdx.x*64, n0 = blockIdx.y*64;
    __shared__ float As[16][64];
    __shared__ float Bk[16][64], Bv[16][64];
    float ak[4][4] = {}, av[4][4] = {};
    int tid = threadIdx.x, tx = tid & 15, ty = tid >> 4;

    for (int k0 = 0; k0 < EE; k0 += 16) {
        #pragma unroll
        for (int i = 0; i < 4; i++) {
            int e = tid + i*256; int m = e >> 4, k = e & 15;
            As[k][m] = X[(size_t)(m0+m)*EE + k0 + k];
        }
        #pragma unroll
        for (int i = 0; i < 4; i++) {
            int e = tid + i*256; int k = e >> 6, n = e & 63;
            Bk[k][n] = Wk[(k0+k)*EE + n0 + n];
            Bv[k][n] = Wv[(k0+k)*EE + n0 + n];
        }
        __syncthreads();
        #pragma unroll
        for (int kk = 0; kk < 16; kk++) {
            float4 a4 = *(const float4*)&As[kk][ty*4];
            float4 k4 = *(const float4*)&Bk[kk][tx*4];
            float4 v4 = *(const float4*)&Bv[kk][tx*4];
            float a[4]  = {a4.x, a4.y, a4.z, a4.w};
            float kb[4] = {k4.x, k4.y, k4.z, k4.w};
            float vb[4] = {v4.x, v4.y, v4.z, v4.w};
            #pragma unroll
            for (int i = 0; i < 4; i++)
                #pragma unroll
                for (int j = 0; j < 4; j++) {
                    ak[i][j] += a[i]*kb[j];
                    av[i][j] += a[i]*vb[j];
                }
        }
        __syncthreads();
    }
    #pragma unroll
    for (int i = 0; i < 4; i++)
        #pragma unroll
        for (int j = 0; j < 4; j++) {
            int row = m0 + ty*4 + i, col = n0 + tx*4 + j;
            size_t o = (size_t)row*EE + col;
            float ekk = __expf(ak[i][j]);
            EK[o]  = ekk;
            EKV[o] = ekk*av[i][j];
        }
}

// ---------------- encoder AFT: y = x + sig(q) * (expA@ekv)/(expA@ek) ----------------
// A[i,j] = exp(s*dist[b,i,j]) generated on the fly (never materialized)
__global__ void aft_enc_kernel(const float* __restrict__ dist,
                               const float* __restrict__ ls,
                               const float* __restrict__ alpha, int l,
                               const float* __restrict__ EKV,
                               const float* __restrict__ EK,
                               const float* __restrict__ X,
                               const float* __restrict__ SQ,
                               float* __restrict__ Y) {
    int b = blockIdx.z;
    const int m0 = blockIdx.x*64, n0 = blockIdx.y*64;
    float s = ls[0]*alpha[l];
    const float* D  = dist + (size_t)b*NN*NN;
    const float* B1 = EKV  + (size_t)b*NN*EE;
    const float* B2 = EK   + (size_t)b*NN*EE;
    __shared__ float As[16][64], Bs1[16][64], Bs2[16][64];
    float a1[4][4] = {}, a2[4][4] = {};
    int tid = threadIdx.x, tx = tid & 15, ty = tid >> 4;

    for (int k0 = 0; k0 < NN; k0 += 16) {
        #pragma unroll
        for (int i = 0; i < 4; i++) {
            int e = tid + i*256; int m = e >> 4, k = e & 15;
            As[k][m] = __expf(s * D[(size_t)(m0+m)*NN + k0 + k]);
        }
        #pragma unroll
        for (int i = 0; i < 4; i++) {
            int e = tid + i*256; int k = e >> 6, n = e & 63;
            Bs1[k][n] = B1[(size_t)(k0+k)*EE + n0 + n];
            Bs2[k][n] = B2[(size_t)(k0+k)*EE + n0 + n];
        }
        __syncthreads();
        #pragma unroll
        for (int kk = 0; kk < 16; kk++) {
            float4 a4  = *(const float4*)&As[kk][ty*4];
            float4 b14 = *(const float4*)&Bs1[kk][tx*4];
            float4 b24 = *(const float4*)&Bs2[kk][tx*4];
            float a[4]  = {a4.x, a4.y, a4.z, a4.w};
            float b1[4] = {b14.x, b14.y, b14.z, b14.w};
            float b2[4] = {b24.x, b24.y, b24.z, b24.w};
            #pragma unroll
            for (int i = 0; i < 4; i++)
                #pragma unroll
                for (int j = 0; j < 4; j++) {
                    a1[i][j] += a[i]*b1[j];
                    a2[i][j] += a[i]*b2[j];
                }
        }
        __syncthreads();
    }
    #pragma unroll
    for (int i = 0; i < 4; i++)
        #pragma unroll
        for (int j = 0; j < 4; j++) {
            int row = m0 + ty*4 + i, col = n0 + tx*4 + j;
            size_t o = ((size_t)b*NN + row)*EE + col;
            Y[o] = X[o] + SQ[o]*(a1[i][j]/a2[i][j]);
        }
}

// ---------------- decoder AFT ----------------
__global__ void dec_aft_kernel(const float* __restrict__ cur_dist,
                               const float* __restrict__ ninf,
                               const float* __restrict__ ls,
                               const float* __restrict__ dalpha,
                               const float* __restrict__ EKV,
                               const float* __restrict__ EK,
                               const float* __restrict__ GQ,
                               const float* __restrict__ cap,
                               const float* __restrict__ dWq,
                               float* __restrict__ AFT) {
    int b = blockIdx.z;
    const int m0 = blockIdx.x*64, n0 = blockIdx.y*64;
    float s = ls[0]*dalpha[0];
    const float* CD = cur_dist + (size_t)b*PP*NN;
    const float* NM = ninf     + (size_t)b*PP*NN;
    const float* B1 = EKV + (size_t)b*NN*EE;
    const float* B2 = EK  + (size_t)b*NN*EE;
    __shared__ float As[16][64], Bs1[16][64], Bs2[16][64];
    float a1[4][4] = {}, a2[4][4] = {};
    int tid = threadIdx.x, tx = tid & 15, ty = tid >> 4;

    for (int k0 = 0; k0 < NN; k0 += 16) {
        #pragma unroll
        for (int i = 0; i < 4; i++) {
            int e = tid + i*256; int m = e >> 4, k = e & 15;
            size_t off = (size_t)(m0+m)*NN + k0 + k;
            As[k][m] = __expf(s*CD[off] + NM[off]);
        }
        #pragma unroll
        for (int i = 0; i < 4; i++) {
            int e = tid + i*256; int k = e >> 6, n = e & 63;
            Bs1[k][n] = B1[(size_t)(k0+k)*EE + n0 + n];
            Bs2[k][n] = B2[(size_t)(k0+k)*EE + n0 + n];
        }
        __syncthreads();
        #pragma unroll
        for (int kk = 0; kk < 16; kk++) {
            float4 a4  = *(const float4*)&As[kk][ty*4];
            float4 b14 = *(const float4*)&Bs1[kk][tx*4];
            float4 b24 = *(const float4*)&Bs2[kk][tx*4];
            float a[4]  = {a4.x, a4.y, a4.z, a4.w};
            float b1[4] = {b14.x, b14.y, b14.z, b14.w};
            float b2[4] = {b24.x, b24.y, b24.z, b24.w};
            #pragma unroll
            for (int i = 0; i < 4; i++)
                #pragma unroll
                for (int j = 0; j < 4; j++) {
                    a1[i][j] += a[i]*b1[j];
                    a2[i][j] += a[i]*b2[j];
                }
        }
        __syncthreads();
    }
    #pragma unroll
    for (int i = 0; i < 4; i++)
        #pragma unroll
        for (int j = 0; j < 4; j++) {
            int p = m0 + ty*4 + i, e = n0 + tx*4 + j;
            float qv = GQ[b*EE + e] + cap[(size_t)b*PP + p]*dWq[EE*EE + e];
            float sg = 1.f/(1.f + __expf(-qv));
            AFT[((size_t)b*PP + p)*EE + e] = sg*(a1[i][j]/a2[i][j]);
        }
}

// ---------------- FF1: hid = relu(h@W1 + b1) ----------------
__global__ void ff1_kernel(const float* __restrict__ H,
                           const float* __restrict__ W1,
                           const float* __restrict__ b1,
                           float* __restrict__ HID) {
    const int m0 = blockIdx.x*64, n0 = blockIdx.y*64;
    __shared__ float As[16][64], Bs[16][64];
    float acc[4][4] = {};
    int tid = threadIdx.x, tx = tid & 15, ty = tid >> 4;
    for (int k0 = 0; k0 < EE; k0 += 16) {
        #pragma unroll
        for (int i = 0; i < 4; i++) {
            int e = tid + i*256; int m = e >> 4, k = e & 15;
            As[k][m] = H[(size_t)(m0+m)*EE + k0 + k];
        }
        #pragma unroll
        for (int i = 0; i < 4; i++) {
            int e = tid + i*256; int k = e >> 6, n = e & 63;
            Bs[k][n] = W1[(k0+k)*FFD + n0 + n];
        }
        __syncthreads();
        #pragma unroll
        for (int kk = 0; kk < 16; kk++) {
            float4 a4 = *(const float4*)&As[kk][ty*4];
            float4 b4 = *(const float4*)&Bs[kk][tx*4];
            float a[4] = {a4.x, a4.y, a4.z, a4.w};
            float bb[4] = {b4.x, b4.y, b4.z, b4.w};
            #pragma unroll
            for (int i = 0; i < 4; i++)
                #pragma unroll
                for (int j = 0; j < 4; j++) acc[i][j] += a[i]*bb[j];
        }
        __syncthreads();
    }
    #pragma unroll
    for (int i = 0; i < 4; i++)
        #pragma unroll
        for (int j = 0; j < 4; j++) {
            int row = m0 + ty*4 + i, col = n0 + tx*4 + j;
            HID[(size_t)row*FFD + col] = fmaxf(acc[i][j] + b1[col], 0.f);
        }
}

// ---------------- FF2: y = h + hid@W2 + b2 ----------------
__global__ void ff2_kernel(const float* __restrict__ HID,
                           const float* __restrict__ W2,
                           const float* __restrict__ b2,
                           const float* __restrict__ H,
                           float* __restrict__ Y) {
    const int m0 = blockIdx.x*64, n0 = blockIdx.y*64;
    __shared__ float As[16][64], Bs[16][64];
    float acc[4][4] = {};
    int tid = threadIdx.x, tx = tid & 15, ty = tid >> 4;
    for (int k0 = 0; k0 < FFD; k0 += 16) {
        #pragma unroll
        for (int i = 0; i < 4; i++) {
            int e = tid + i*256; int m = e >> 4, k = e & 15;
            As[k][m] = HID[(size_t)(m0+m)*FFD + k0 + k];
        }
        #pragma unroll
        for (int i = 0; i < 4; i++) {
            int e = tid + i*256; int k = e >> 6, n = e & 63;
            Bs[k][n] = W2[(k0+k)*EE + n0 + n];
        }
        __syncthreads();
        #pragma unroll
        for (int kk = 0; kk < 16; kk++) {
            float4 a4 = *(const float4*)&As[kk][ty*4];
            float4 b4 = *(const float4*)&Bs[kk][tx*4];
            float a[4] = {a4.x, a4.y, a4.z, a4.w};
            float bb[4] = {b4.x, b4.y, b4.z, b4.w};
            #pragma unroll
            for (int i = 0; i < 4; i++)
                #pragma unroll
                for (int j = 0; j < 4; j++) acc[i][j] += a[i]*bb[j];
        }
        __syncthreads();
    }
    #pragma unroll
    for (int i = 0; i < 4; i++)
        #pragma unroll
        for (int j = 0; j < 4; j++) {
            int row = m0 + ty*4 + i, col = n0 + tx*4 + j;
            size_t o = (size_t)row*EE + col;
            Y[o] = H[o] + acc[i][j] + b2[col];
        }
}

// ---------------- instance norm over node dim (axis=1) ----------------
__global__ void inorm_kernel(const float* __restrict__ src,
                             float* __restrict__ dst,
                             const float* __restrict__ w,
                             const float* __restrict__ bias) {
    int b = blockIdx.x;
    int e = threadIdx.x;   // 0..127
    int c = threadIdx.y;   // 0..7
    const float* S = src + (size_t)b*NN*EE;
    float s = 0.f, s2 = 0.f;
    for (int n = c*64; n < c*64 + 64; n++) {
        float v = S[(size_t)n*EE + e];
        s += v; s2 += v*v;
    }
    __shared__ float ssum[8][128], ssq[8][128];
    __shared__ float smu[128], srs[128];
    ssum[c][e] = s; ssq[c][e] = s2;
    __syncthreads();
    if (c == 0) {
        float ts = 0.f, t2 = 0.f;
        #pragma unroll
        for (int i = 0; i < 8; i++) { ts += ssum[i][e]; t2 += ssq[i][e]; }
        float mu = ts*(1.f/NN);
        float var = t2*(1.f/NN) - mu*mu;
        smu[e] = mu;
        srs[e] = rsqrtf(var + EPS);
    }
    __syncthreads();
    float mu = smu[e], rs = srs[e], ww = w[e], bb = bias[e];
    float* Dd = dst + (size_t)b*NN*EE;
    for (int n = c*64; n < c*64 + 64; n++) {
        size_t o = (size_t)n*EE + e;
        Dd[o] = (S[o] - mu)*rs*ww + bb;
    }
}

// ---------------- graph mean over nodes ----------------
__global__ void gmean_kernel(const float* __restrict__ X, float* __restrict__ GM) {
    int b = blockIdx.x, e = threadIdx.x, c = threadIdx.y;
    float s = 0.f;
    for (int n = c*64; n < c*64 + 64; n++)
        s += X[((size_t)b*NN + n)*EE + e];
    __shared__ float sm[8][128];
    sm[c][e] = s;
    __syncthreads();
    if (c == 0) {
        float t = 0.f;
        #pragma unroll
        for (int i = 0; i < 8; i++) t += sm[i][e];
        GM[b*EE + e] = t*(1.f/NN);
    }
}

// ---------------- gq = gmean @ dWq[0:E,:] ----------------
__global__ void gq_kernel(const float* __restrict__ GM,
                          const float* __restrict__ dWq,
                          float* __restrict__ GQ) {
    int b = blockIdx.x, e = threadIdx.x;
    float acc = 0.f;
    for (int i = 0; i < EE; i++)
        acc += GM[b*EE + i]*dWq[i*EE + e];
    GQ[b*EE + e] = acc;
}

// ---------------- score GEMM: S = aft @ enc^T (NT) + epilogue ----------------
__global__ void score_kernel(const float* __restrict__ AFT,
                             const float* __restrict__ ENC,
                             const float* __restrict__ cur_dist,
                             const float* __restrict__ ninf,
                             const float* __restrict__ ls,
                             const float* __restrict__ palpha,
                             float* __restrict__ OUT) {
    int b = blockIdx.z;
    const int p0 = blockIdx.x*64, n0 = blockIdx.y*64;
    float ps = ls[0]*palpha[0];
    const float* A = AFT + (size_t)b*PP*EE;
    const float* Eb = ENC + (size_t)b*NN*EE;
    __shared__ float As[16][64], Bs[16][64];
    float acc[4][4] = {};
    int tid = threadIdx.x, tx = tid & 15, ty = tid >> 4;
    for (int k0 = 0; k0 < EE; k0 += 16) {
        #pragma unroll
        for (int i = 0; i < 4; i++) {
            int e = tid + i*256; int m = e >> 4, k = e & 15;
            As[k][m] = A[(size_t)(p0+m)*EE + k0 + k];
        }
        #pragma unroll
        for (int i = 0; i < 4; i++) {
            int e = tid + i*256; int kk = e & 15, nn = e >> 4;
            Bs[kk][nn] = Eb[(size_t)(n0+nn)*EE + k0 + kk];
        }
        __syncthreads();
        #pragma unroll
        for (int kk = 0; kk < 16; kk++) {
            float4 a4 = *(const float4*)&As[kk][ty*4];
            float4 b4 = *(const float4*)&Bs[kk][tx*4];
            float a[4] = {a4.x, a4.y, a4.z, a4.w};
            float bb[4] = {b4.x, b4.y, b4.z, b4.w};
            #pragma unroll
            for (int i = 0; i < 4; i++)
                #pragma unroll
                for (int j = 0; j < 4; j++) acc[i][j] += a[i]*bb[j];
        }
        __syncthreads();
    }
    #pragma unroll
    for (int i = 0; i < 4; i++)
        #pragma unroll
        for (int j = 0; j < 4; j++) {
            int p = p0 + ty*4 + i, n = n0 + tx*4 + j;
            size_t o = ((size_t)b*PP + p)*NN + n;
            float sc = acc[i][j]*INV_SQRT_E + ps*cur_dist[o];
            OUT[o] = 10.f*tanhf(sc) + ninf[o];
        }
}

// ---------------- row softmax over last dim (512) ----------------
__global__ void softmax_kernel(float* __restrict__ OUT) {
    float* row = OUT + (size_t)blockIdx.x*NN;
    int t = threadIdx.x;              // 128 threads
    float v[4];
    #pragma unroll
    for (int i = 0; i < 4; i++) v[i] = row[t + i*128];
    float m = fmaxf(fmaxf(v[0], v[1]), fmaxf(v[2], v[3]));
    __shared__ float red[4];
    #pragma unroll
    for (int off = 16; off > 0; off >>= 1)
        m = fmaxf(m, __shfl_xor_sync(0xffffffff, m, off));
    if ((t & 31) == 0) red[t >> 5] = m;
    __syncthreads();
    m = fmaxf(fmaxf(red[0], red[1]), fmaxf(red[2], red[3]));
    __syncthreads();
    float s = 0.f;
    #pragma unroll
    for (int i = 0; i < 4; i++) { v[i] = __expf(v[i] - m); s += v[i]; }
    #pragma unroll
    for (int off = 16; off > 0; off >>= 1)
        s += __shfl_xor_sync(0xffffffff, s, off);
    if ((t & 31) == 0) red[t >> 5] = s;
    __syncthreads();
    s = red[0] + red[1] + red[2] + red[3];
    float inv = 1.f/s;
    #pragma unroll
    for (int i = 0; i < 4; i++) row[t + i*128] = v[i]*inv;
}

// ---------------- launch ----------------
extern "C" void kernel_launch(void* const* d_in, const int* in_sizes, int n_in,
                              void* d_out, int out_size) {
    const float* data      = (const float*)d_in[0];
    const float* dist      = (const float*)d_in[1];
    const float* cur_dist  = (const float*)d_in[2];
    const float* capacity  = (const float*)d_in[3];
    const float* ninf_mask = (const float*)d_in[4];
    const float* log_scale = (const float*)d_in[5];
    const float* emb_W     = (const float*)d_in[6];
    const float* emb_b     = (const float*)d_in[7];
    const float* Wq        = (const float*)d_in[8];
    const float* Wk        = (const float*)d_in[9];
    const float* Wv        = (const float*)d_in[10];
    const float* aft_alpha = (const float*)d_in[11];
    const float* n1_w      = (const float*)d_in[12];
    const float* n1_b      = (const float*)d_in[13];
    const float* ff_W1     = (const float*)d_in[14];
    const float* ff_b1     = (const float*)d_in[15];
    const float* ff_W2     = (const float*)d_in[16];
    const float* ff_b2     = (const float*)d_in[17];
    const float* n2_w      = (const float*)d_in[18];
    const float* n2_b      = (const float*)d_in[19];
    const float* dWq       = (const float*)d_in[20];
    const float* dWk       = (const float*)d_in[21];
    const float* dWv       = (const float*)d_in[22];
    const float* dec_alpha = (const float*)d_in[23];
    const float* p_alpha   = (const float*)d_in[24];
    float* out = (float*)d_out;

    float *x, *y, *h, *sq, *ek, *ekv, *hid, *aft, *gq, *gm;
    cudaGetSymbolAddress((void**)&x,   g_x);
    cudaGetSymbolAddress((void**)&y,   g_y);
    cudaGetSymbolAddress((void**)&h,   g_h);
    cudaGetSymbolAddress((void**)&sq,  g_sq);
    cudaGetSymbolAddress((void**)&ek,  g_ek);
    cudaGetSymbolAddress((void**)&ekv, g_ekv);
    cudaGetSymbolAddress((void**)&hid, g_hid);
    cudaGetSymbolAddress((void**)&aft, g_aft);
    cudaGetSymbolAddress((void**)&gq,  g_gq);
    cudaGetSymbolAddress((void**)&gm,  g_gm);

    embed_kernel<<<M_TOT, EE>>>(data, emb_W, emb_b, x);

    for (int l = 0; l < LLAYERS; l++) {
        qkv_kernel<<<dim3(M_TOT/64, EE/64), 256>>>(
            x, Wq + (size_t)l*EE*EE, Wk + (size_t)l*EE*EE, Wv + (size_t)l*EE*EE,
            sq, ek, ekv);
        aft_enc_kernel<<<dim3(NN/64, EE/64, BB), 256>>>(
            dist, log_scale, aft_alpha, l, ekv, ek, x, sq, y);
        inorm_kernel<<<BB, dim3(128, 8)>>>(y, h, n1_w + l*EE, n1_b + l*EE);
        ff1_kernel<<<dim3(M_TOT/64, FFD/64), 256>>>(
            h, ff_W1 + (size_t)l*EE*FFD, ff_b1 + l*FFD, hid);
        ff2_kernel<<<dim3(M_TOT/64, EE/64), 256>>>(
            hid, ff_W2 + (size_t)l*FFD*EE, ff_b2 + l*EE, h, y);
        inorm_kernel<<<BB, dim3(128, 8)>>>(y, x, n2_w + l*EE, n2_b + l*EE);
    }

    // decoder
    deckv_kernel<<<dim3(M_TOT/64, EE/64), 256>>>(x, dWk, dWv, ek, ekv);
    gmean_kernel<<<BB, dim3(128, 8)>>>(x, gm);
    gq_kernel<<<BB, 128>>>(gm, dWq, gq);
    dec_aft_kernel<<<dim3(PP/64, EE/64, BB), 256>>>(
        cur_dist, ninf_mask, log_scale, dec_alpha, ekv, ek, gq, capacity, dWq, aft);
    score_kernel<<<dim3(PP/64, NN/64, BB), 256>>>(
        aft, x, cur_dist, ninf_mask, log_scale, p_alpha, out);
    softmax_kernel<<<BB*PP, 128>>>(out);
}